// round 12
// baseline (speedup 1.0000x reference)
#include <cuda_runtime.h>

// ============================================================================
// AdditiveAttention: out = softmax_k( sum_h w_v[h]*tanh(qW_q + kW_k) ) @ V
// B=16, NQ=64, NK=512, QS=KS=H=VD=256, fp32.
//
// R12: one-MUFU-per-element scores via the tanh addition identity.
// Measured MUFU costs (R8/R11): TANH ~29 cyc, EX2/RCP ~17 cyc per warp-op.
//   tanh(q+k) = (tq + tk) / (1 + tq*tk),  tq/tk = accurate tanh of the
//   projections, computed once in the projection epilogue (2.4M elems).
// Inner loop/elem: FFMA(den) FADD(num) MUFU.RCP FMUL FFMA(acc) -> 1 MUFU.
// Layout identical to R8 (lane=key, 8 queries/warp, cp.async h-chunks of 32).
// ============================================================================

#define C2SCALE 2.885390081777927f   // 2*log2(e)

// scratch (allocation-free rule -> __device__ globals)
__device__ float g_qh[16 * 64 * 256];    // 4 MB: tanh(queries @ W_q)
__device__ float g_kh[16 * 512 * 256];   // 8 MB: tanh(keys @ W_k)

__device__ __forceinline__ float ex2_fast(float x) {
    float r; asm("ex2.approx.f32 %0, %1;" : "=f"(r) : "f"(x)); return r;
}
__device__ __forceinline__ float rcp_fast(float x) {
    float r; asm("rcp.approx.f32 %0, %1;" : "=f"(r) : "f"(x)); return r;
}
// accurate tanh: err ~2e-7 (used only in projection epilogue)
__device__ __forceinline__ float tanh_acc(float x) {
    float e = ex2_fast(x * C2SCALE);            // e^(2x)
    return 1.0f - 2.0f * rcp_fast(1.0f + e);
}
__device__ __forceinline__ void cp_async16(void* smem_dst, const void* gmem_src) {
    unsigned s = (unsigned)__cvta_generic_to_shared(smem_dst);
    asm volatile("cp.async.cg.shared.global [%0], [%1], 16;\n" :: "r"(s), "l"(gmem_src));
}
__device__ __forceinline__ void cp_async_commit() {
    asm volatile("cp.async.commit_group;\n" ::);
}
__device__ __forceinline__ void cp_async_wait1() {
    asm volatile("cp.async.wait_group 1;\n" ::);
}
__device__ __forceinline__ void cp_async_wait0() {
    asm volatile("cp.async.wait_group 0;\n" ::);
}

// ----------------------------------------------------------------------------
// Merged projection SGEMM, epilogue stores tanh(acc).
// Logical M = 1024 (queries) + 8192 (keys); N = 256, K = 256.
// BM=128, BN=128, BK=16, 256 threads, 8x8 micro-tile. Grid (2,72) = one wave.
// ----------------------------------------------------------------------------
#define PJ_PAD 132

__global__ __launch_bounds__(256, 1)
void proj_kernel(const float* __restrict__ queries,
                 const float* __restrict__ keys,
                 const float* __restrict__ Wq,
                 const float* __restrict__ Wk,
                 float* __restrict__ qh,
                 float* __restrict__ kh) {
    __shared__ float As[16 * PJ_PAD];   // [k][m] transposed, padded
    __shared__ float Ws[16 * PJ_PAD];   // [k][n], padded

    const int tid = threadIdx.x;
    const int tx  = tid & 15;
    const int ty  = tid >> 4;
    const int bm  = blockIdx.y * 128;
    const int bn  = blockIdx.x * 128;

    const float* A; const float* W; float* C; int rowbase;
    if (bm < 1024) { A = queries; W = Wq; C = qh; rowbase = bm; }
    else           { A = keys;    W = Wk; C = kh; rowbase = bm - 1024; }

    const int ar0 = tid >> 2;
    const int ac  = (tid & 3) * 4;
    const int wr0 = tid >> 5;
    const int wc  = (tid & 31) * 4;

    float acc[8][8] = {};

    for (int k0 = 0; k0 < 256; k0 += 16) {
        float4 a0 = *(const float4*)&A[(rowbase + ar0)      * 256 + k0 + ac];
        float4 a1 = *(const float4*)&A[(rowbase + ar0 + 64) * 256 + k0 + ac];
        float4 w0 = *(const float4*)&W[(k0 + wr0)     * 256 + bn + wc];
        float4 w1 = *(const float4*)&W[(k0 + wr0 + 8) * 256 + bn + wc];

        As[(ac + 0) * PJ_PAD + ar0]      = a0.x;
        As[(ac + 1) * PJ_PAD + ar0]      = a0.y;
        As[(ac + 2) * PJ_PAD + ar0]      = a0.z;
        As[(ac + 3) * PJ_PAD + ar0]      = a0.w;
        As[(ac + 0) * PJ_PAD + ar0 + 64] = a1.x;
        As[(ac + 1) * PJ_PAD + ar0 + 64] = a1.y;
        As[(ac + 2) * PJ_PAD + ar0 + 64] = a1.z;
        As[(ac + 3) * PJ_PAD + ar0 + 64] = a1.w;
        *(float4*)&Ws[ wr0      * PJ_PAD + wc] = w0;
        *(float4*)&Ws[(wr0 + 8) * PJ_PAD + wc] = w1;
        __syncthreads();

        #pragma unroll
        for (int kk = 0; kk < 16; ++kk) {
            float a[8], b[8];
            *(float4*)&a[0] = *(const float4*)&As[kk * PJ_PAD + ty * 8];
            *(float4*)&a[4] = *(const float4*)&As[kk * PJ_PAD + ty * 8 + 4];
            *(float4*)&b[0] = *(const float4*)&Ws[kk * PJ_PAD + tx * 8];
            *(float4*)&b[4] = *(const float4*)&Ws[kk * PJ_PAD + tx * 8 + 4];
            #pragma unroll
            for (int i = 0; i < 8; ++i)
                #pragma unroll
                for (int j = 0; j < 8; ++j)
                    acc[i][j] = fmaf(a[i], b[j], acc[i][j]);
        }
        __syncthreads();
    }

    #pragma unroll
    for (int i = 0; i < 8; ++i) {
        float* dst = &C[(rowbase + ty * 8 + i) * 256 + bn + tx * 8];
        float4 o0 = make_float4(tanh_acc(acc[i][0]), tanh_acc(acc[i][1]),
                                tanh_acc(acc[i][2]), tanh_acc(acc[i][3]));
        float4 o1 = make_float4(tanh_acc(acc[i][4]), tanh_acc(acc[i][5]),
                                tanh_acc(acc[i][6]), tanh_acc(acc[i][7]));
        *(float4*)&dst[0] = o0;
        *(float4*)&dst[4] = o1;
    }
}

// ----------------------------------------------------------------------------
// Fused scores + masked softmax + attn@V  (R8 layout, rational tanh merge).
// Grid: 128 blocks = (b, 8-query tile).  Block: 512 threads = 16 warps.
// Warp w owns keys [w*32, w*32+32) (lane = one key), computes all 8 queries.
// Keys (tanh'd) staged in h-chunks of 32, stride 36, double-buffered cp.async.
// ----------------------------------------------------------------------------
#define KB_STRIDE 36
#define NKEY 512
#define KBUF_FLOATS (NKEY * KB_STRIDE)          // 18432 per buffer
#define ATTN_SMEM_FLOATS (2 * KBUF_FLOATS + 8 * 256 + 256 + 8 * 512 + 128 + 16)
#define ATTN_SMEM_BYTES  (ATTN_SMEM_FLOATS * 4)

__global__ __launch_bounds__(512, 1)
void attn_kernel(const float* __restrict__ values,
                 const int* __restrict__ valid_lens,
                 const float* __restrict__ w_v,
                 float* __restrict__ out) {
    extern __shared__ float sm[];
    float* kbuf   = sm;                          // 2 x 512 x 36 (double buf)
    float* qh_s   = kbuf + 2 * KBUF_FLOATS;      // 8 x 256   (tq)
    float* wv_s   = qh_s + 8 * 256;              // 256       (w_v)
    float* attn_s = wv_s + 256;                  // 8 x 512
    float* red1   = attn_s + 8 * 512;            // 128: per-(q,warp) partials
    float* fin_s  = red1 + 128;                  // [0..7] max, [8..15] 1/sum

    const int tid  = threadIdx.x;
    const int b    = blockIdx.x >> 3;
    const int q0   = (blockIdx.x & 7) * 8;
    const int w    = tid >> 5;
    const int lane = tid & 31;
    const int key  = w * 32 + lane;             // this lane's key (fixed)
    const int vlen = valid_lens[b];

    // stage 8 query rows (tq, one float4 per thread) and w_v
    *(float4*)&qh_s[tid * 4] =
        *(const float4*)&g_qh[((size_t)(b * 64 + q0)) * 256 + tid * 4];
    if (tid < 64)
        *(float4*)&wv_s[tid * 4] = *(const float4*)&w_v[tid * 4];

    // cp.async staging: chunk c -> kbuf[(c&1)*KBUF].  Thread tid stages the
    // 32 floats (tk) of key==tid: 8 x 16B.
    const float* khg = &g_kh[(size_t)b * 512 * 256 + (size_t)tid * 256];
    #pragma unroll
    for (int pre = 0; pre < 2; ++pre) {
        float* dst = &kbuf[pre * KBUF_FLOATS + tid * KB_STRIDE];
        const float* src = &khg[pre * 32];
        #pragma unroll
        for (int j = 0; j < 8; ++j)
            cp_async16(&dst[j * 4], &src[j * 4]);
        cp_async_commit();
    }

    float sc[8] = {0.f, 0.f, 0.f, 0.f, 0.f, 0.f, 0.f, 0.f};

    #pragma unroll 1
    for (int c = 0; c < 8; ++c) {
        if (c < 7) cp_async_wait1(); else cp_async_wait0();
        __syncthreads();

        const float* kb = &kbuf[(c & 1) * KBUF_FLOATS + key * KB_STRIDE];
        const int hbase = c * 32;

        #pragma unroll 2
        for (int i = 0; i < 8; ++i) {
            float4 kv = *(const float4*)&kb[i * 4];
            float4 w4 = *(const float4*)&wv_s[hbase + i * 4];
            #pragma unroll
            for (int q = 0; q < 8; ++q) {
                float4 qv = *(const float4*)&qh_s[q * 256 + hbase + i * 4];
                // tanh(q+k) = (tq+tk) * rcp(1 + tq*tk)
                float t0 = (qv.x + kv.x) * rcp_fast(fmaf(qv.x, kv.x, 1.0f));
                float t1 = (qv.y + kv.y) * rcp_fast(fmaf(qv.y, kv.y, 1.0f));
                float t2 = (qv.z + kv.z) * rcp_fast(fmaf(qv.z, kv.z, 1.0f));
                float t3 = (qv.w + kv.w) * rcp_fast(fmaf(qv.w, kv.w, 1.0f));
                sc[q] = fmaf(w4.x, t0, sc[q]);
                sc[q] = fmaf(w4.y, t1, sc[q]);
                sc[q] = fmaf(w4.z, t2, sc[q]);
                sc[q] = fmaf(w4.w, t3, sc[q]);
            }
        }

        __syncthreads();
        if (c < 6) {   // prefetch chunk c+2 into the buffer just freed
            float* dst = &kbuf[(c & 1) * KBUF_FLOATS + tid * KB_STRIDE];
            const float* src = &khg[(c + 2) * 32];
            #pragma unroll
            for (int j = 0; j < 8; ++j)
                cp_async16(&dst[j * 4], &src[j * 4]);
            cp_async_commit();
        }
    }

    // ---- masked softmax over keys (per query) ----
    #pragma unroll
    for (int q = 0; q < 8; ++q) {
        float v = sc[q];
        if (key >= vlen) v = -1e30f;
        sc[q] = v;
        #pragma unroll
        for (int o = 16; o; o >>= 1) v = fmaxf(v, __shfl_xor_sync(0xffffffffu, v, o));
        if (lane == 0) red1[q * 16 + w] = v;
    }
    __syncthreads();
    if (tid < 128) {           // 16-lane groups finalize per-q max
        const int q = tid >> 4, i = tid & 15;
        float v = red1[q * 16 + i];
        #pragma unroll
        for (int o = 8; o; o >>= 1) v = fmaxf(v, __shfl_xor_sync(0xffffffffu, v, o));
        if (i == 0) fin_s[q] = v;
    }
    __syncthreads();

    float p[8];
    #pragma unroll
    for (int q = 0; q < 8; ++q) {
        p[q] = ex2_fast((sc[q] - fin_s[q]) * 1.4426950408889634f);
        float v = p[q];
        #pragma unroll
        for (int o = 16; o; o >>= 1) v += __shfl_xor_sync(0xffffffffu, v, o);
        if (lane == 0) red1[q * 16 + w] = v;
    }
    __syncthreads();
    if (tid < 128) {
        const int q = tid >> 4, i = tid & 15;
        float v = red1[q * 16 + i];
        #pragma unroll
        for (int o = 8; o; o >>= 1) v += __shfl_xor_sync(0xffffffffu, v, o);
        if (i == 0) fin_s[8 + q] = rcp_fast(v);
    }
    __syncthreads();

    #pragma unroll
    for (int q = 0; q < 8; ++q)
        attn_s[q * 512 + key] = p[q] * fin_s[8 + q];
    __syncthreads();

    // ------ output: out[b, q0+qq, v] = sum_k attn[qq][k] * values[b,k,v] ------
    const int half = tid >> 8;          // 0: q0..q0+3, 1: q0+4..q0+7
    const int v    = tid & 255;
    const float* vp = values + (size_t)b * 512 * 256 + v;
    const float* a0 = &attn_s[(half * 4 + 0) * 512];
    const float* a1 = a0 + 512;
    const float* a2 = a1 + 512;
    const float* a3 = a2 + 512;
    float o0 = 0.f, o1 = 0.f, o2 = 0.f, o3 = 0.f;
    #pragma unroll 4
    for (int k = 0; k < vlen; ++k) {
        float vv = vp[(size_t)k * 256];
        o0 = fmaf(a0[k], vv, o0);
        o1 = fmaf(a1[k], vv, o1);
        o2 = fmaf(a2[k], vv, o2);
        o3 = fmaf(a3[k], vv, o3);
    }
    float* op = out + ((size_t)b * 64 + q0 + half * 4) * 256 + v;
    op[0]   = o0;
    op[256] = o1;
    op[512] = o2;
    op[768] = o3;
}

// ----------------------------------------------------------------------------
extern "C" void kernel_launch(void* const* d_in, const int* in_sizes, int n_in,
                              void* d_out, int out_size) {
    (void)in_sizes; (void)n_in; (void)out_size;
    const float* queries = (const float*)d_in[0];   // [16,64,256]
    const float* keys    = (const float*)d_in[1];   // [16,512,256]
    const float* values  = (const float*)d_in[2];   // [16,512,256]
    const int*   vlens   = (const int*)  d_in[3];   // [16]
    const float* Wq      = (const float*)d_in[4];   // [256,256]
    const float* Wk      = (const float*)d_in[5];   // [256,256]
    const float* wv      = (const float*)d_in[6];   // [256]
    float* out = (float*)d_out;                     // [16,64,256]

    float *qh = nullptr, *kh = nullptr;
    cudaGetSymbolAddress((void**)&qh, g_qh);
    cudaGetSymbolAddress((void**)&kh, g_kh);

    cudaFuncSetAttribute(attn_kernel,
                         cudaFuncAttributeMaxDynamicSharedMemorySize,
                         ATTN_SMEM_BYTES);

    proj_kernel<<<dim3(2, 72), 256>>>(queries, keys, Wq, Wk, qh, kh);
    attn_kernel<<<128, 512, ATTN_SMEM_BYTES>>>(values, vlens, wv, out);
}

// round 13
// speedup vs baseline: 1.3603x; 1.3603x over previous
#include <cuda_runtime.h>

// ============================================================================
// AdditiveAttention: out = softmax_k( sum_h w_v[h]*tanh(qW_q + kW_k) ) @ V
// B=16, NQ=64, NK=512, QS=KS=H=VD=256, fp32.
//
// R13: exploit masking via split-K partial softmax.
// valid_lens ~ U[1,512] (mean ~256) -> ~47% of score work is masked away, but
// the old 1-wave grid made wall time = the full-vlen block. New grid:
//   (b, qtile8, ksplit4) = 512 blocks of 8q x 128 keys, 128 thr, occ 4.
//   - block fully masked (kbase >= vlen): write m=-1e30, s=0, exit.
//   - warp fully masked: skip score compute.
// Each block writes unnormalized partials (m, s, o[8x256]) -> combine kernel
// merges the 4 k-splits per query row (log-sum-exp merge).
// Inner loop = R8's proven 3-instr/elem MUFU.TANH form.
// ============================================================================

// scratch (allocation-free rule -> __device__ globals; zero-initialized)
__device__ float g_qh[16 * 64 * 256];        // 4 MB: queries @ W_q
__device__ float g_kh[16 * 512 * 256];       // 8 MB: keys @ W_k
__device__ float g_po[512 * 8 * 256];        // 4 MB: partial outputs
__device__ float g_pm[512 * 8];              // partial maxes
__device__ float g_ps[512 * 8];              // partial sums

#define L2E 1.4426950408889634f

__device__ __forceinline__ float tanh_fast(float x) {
    float r; asm("tanh.approx.f32 %0, %1;" : "=f"(r) : "f"(x)); return r;
}
__device__ __forceinline__ float ex2_fast(float x) {
    float r; asm("ex2.approx.f32 %0, %1;" : "=f"(r) : "f"(x)); return r;
}
__device__ __forceinline__ float rcp_fast(float x) {
    float r; asm("rcp.approx.f32 %0, %1;" : "=f"(r) : "f"(x)); return r;
}
__device__ __forceinline__ void cp_async16(void* smem_dst, const void* gmem_src) {
    unsigned s = (unsigned)__cvta_generic_to_shared(smem_dst);
    asm volatile("cp.async.cg.shared.global [%0], [%1], 16;\n" :: "r"(s), "l"(gmem_src));
}
__device__ __forceinline__ void cp_async_commit() {
    asm volatile("cp.async.commit_group;\n" ::);
}
__device__ __forceinline__ void cp_async_wait1() {
    asm volatile("cp.async.wait_group 1;\n" ::);
}
__device__ __forceinline__ void cp_async_wait0() {
    asm volatile("cp.async.wait_group 0;\n" ::);
}

// ----------------------------------------------------------------------------
// Merged projection SGEMM (unchanged from R8).
// ----------------------------------------------------------------------------
#define PJ_PAD 132

__global__ __launch_bounds__(256, 1)
void proj_kernel(const float* __restrict__ queries,
                 const float* __restrict__ keys,
                 const float* __restrict__ Wq,
                 const float* __restrict__ Wk,
                 float* __restrict__ qh,
                 float* __restrict__ kh) {
    __shared__ float As[16 * PJ_PAD];
    __shared__ float Ws[16 * PJ_PAD];

    const int tid = threadIdx.x;
    const int tx  = tid & 15;
    const int ty  = tid >> 4;
    const int bm  = blockIdx.y * 128;
    const int bn  = blockIdx.x * 128;

    const float* A; const float* W; float* C; int rowbase;
    if (bm < 1024) { A = queries; W = Wq; C = qh; rowbase = bm; }
    else           { A = keys;    W = Wk; C = kh; rowbase = bm - 1024; }

    const int ar0 = tid >> 2;
    const int ac  = (tid & 3) * 4;
    const int wr0 = tid >> 5;
    const int wc  = (tid & 31) * 4;

    float acc[8][8] = {};

    for (int k0 = 0; k0 < 256; k0 += 16) {
        float4 a0 = *(const float4*)&A[(rowbase + ar0)      * 256 + k0 + ac];
        float4 a1 = *(const float4*)&A[(rowbase + ar0 + 64) * 256 + k0 + ac];
        float4 w0 = *(const float4*)&W[(k0 + wr0)     * 256 + bn + wc];
        float4 w1 = *(const float4*)&W[(k0 + wr0 + 8) * 256 + bn + wc];

        As[(ac + 0) * PJ_PAD + ar0]      = a0.x;
        As[(ac + 1) * PJ_PAD + ar0]      = a0.y;
        As[(ac + 2) * PJ_PAD + ar0]      = a0.z;
        As[(ac + 3) * PJ_PAD + ar0]      = a0.w;
        As[(ac + 0) * PJ_PAD + ar0 + 64] = a1.x;
        As[(ac + 1) * PJ_PAD + ar0 + 64] = a1.y;
        As[(ac + 2) * PJ_PAD + ar0 + 64] = a1.z;
        As[(ac + 3) * PJ_PAD + ar0 + 64] = a1.w;
        *(float4*)&Ws[ wr0      * PJ_PAD + wc] = w0;
        *(float4*)&Ws[(wr0 + 8) * PJ_PAD + wc] = w1;
        __syncthreads();

        #pragma unroll
        for (int kk = 0; kk < 16; ++kk) {
            float a[8], b[8];
            *(float4*)&a[0] = *(const float4*)&As[kk * PJ_PAD + ty * 8];
            *(float4*)&a[4] = *(const float4*)&As[kk * PJ_PAD + ty * 8 + 4];
            *(float4*)&b[0] = *(const float4*)&Ws[kk * PJ_PAD + tx * 8];
            *(float4*)&b[4] = *(const float4*)&Ws[kk * PJ_PAD + tx * 8 + 4];
            #pragma unroll
            for (int i = 0; i < 8; ++i)
                #pragma unroll
                for (int j = 0; j < 8; ++j)
                    acc[i][j] = fmaf(a[i], b[j], acc[i][j]);
        }
        __syncthreads();
    }

    #pragma unroll
    for (int i = 0; i < 8; ++i) {
        float* dst = &C[(rowbase + ty * 8 + i) * 256 + bn + tx * 8];
        *(float4*)&dst[0] = *(float4*)&acc[i][0];
        *(float4*)&dst[4] = *(float4*)&acc[i][4];
    }
}

// ----------------------------------------------------------------------------
// Partial-attention kernel.
// Grid: 512 = b*32 + qt*4 + ks.   Block: 128 threads = 4 warps.
// Warp w owns keys kbase + w*32 + lane; computes 8 queries.
// Keys staged in h-chunks of 32 (stride 36), double-buffered cp.async.
// Emits m/s/o partials (unnormalized softmax over this block's valid keys).
// ----------------------------------------------------------------------------
#define KB_STRIDE 36
#define KEYS_PB 128
#define KBUF_FLOATS (KEYS_PB * KB_STRIDE)       // 4608 per buffer
#define PA_SMEM_FLOATS (2 * KBUF_FLOATS + 8 * 256 + 256 + 8 * KEYS_PB + 32 + 8)
#define PA_SMEM_BYTES  (PA_SMEM_FLOATS * 4)

__global__ __launch_bounds__(128, 4)
void attn_partial_kernel(const float* __restrict__ values,
                         const int* __restrict__ valid_lens,
                         const float* __restrict__ w_v) {
    extern __shared__ float sm[];
    float* kbuf   = sm;                          // 2 x 128 x 36
    float* qh_s   = kbuf + 2 * KBUF_FLOATS;      // 8 x 256
    float* wv_s   = qh_s + 8 * 256;              // 256
    float* attn_s = wv_s + 256;                  // 8 x 128 (unnormalized p)
    float* red1   = attn_s + 8 * KEYS_PB;        // 32: (q,warp) partials
    float* fin_s  = red1 + 32;                   // [0..7] per-q max

    const int tid   = threadIdx.x;
    const int bx    = blockIdx.x;
    const int b     = bx >> 5;
    const int qt    = (bx >> 2) & 7;
    const int ks    = bx & 3;
    const int kbase = ks * KEYS_PB;
    const int vlen  = valid_lens[b];

    // fully masked block: record empty partial and exit (uniform branch)
    if (kbase >= vlen) {
        if (tid < 8) {
            g_pm[bx * 8 + tid] = -1e30f;
            g_ps[bx * 8 + tid] = 0.0f;
        }
        return;   // g_po region stays 0 (never written; zero-init globals)
    }

    const int w    = tid >> 5;
    const int lane = tid & 31;
    const int key  = kbase + tid;               // this thread's key
    const bool stage_ok   = key < vlen;
    const bool warp_live  = (kbase + w * 32) < vlen;
    const int q0   = qt * 8;

    // stage 8 query rows (2048 floats) and w_v
    for (int i = tid; i < 512; i += 128)
        *(float4*)&qh_s[i * 4] =
            *(const float4*)&g_qh[((size_t)(b * 64 + q0)) * 256 + i * 4];
    if (tid < 64)
        *(float4*)&wv_s[tid * 4] = *(const float4*)&w_v[tid * 4];

    // cp.async staging: chunk c = 32 h-floats of this thread's key
    const float* khg = &g_kh[((size_t)b * 512 + key) * 256];
    #pragma unroll
    for (int pre = 0; pre < 2; ++pre) {
        if (stage_ok) {
            float* dst = &kbuf[pre * KBUF_FLOATS + tid * KB_STRIDE];
            const float* src = &khg[pre * 32];
            #pragma unroll
            for (int j = 0; j < 8; ++j)
                cp_async16(&dst[j * 4], &src[j * 4]);
        }
        cp_async_commit();
    }

    float sc[8] = {0.f, 0.f, 0.f, 0.f, 0.f, 0.f, 0.f, 0.f};

    #pragma unroll 1
    for (int c = 0; c < 8; ++c) {
        if (c < 7) cp_async_wait1(); else cp_async_wait0();
        __syncthreads();

        if (warp_live) {
            const float* kb = &kbuf[(c & 1) * KBUF_FLOATS + tid * KB_STRIDE];
            const int hbase = c * 32;
            #pragma unroll 2
            for (int i = 0; i < 8; ++i) {
                float4 kv = *(const float4*)&kb[i * 4];
                float4 w4 = *(const float4*)&wv_s[hbase + i * 4];
                #pragma unroll
                for (int q = 0; q < 8; ++q) {
                    float4 qv = *(const float4*)&qh_s[q * 256 + hbase + i * 4];
                    sc[q] = fmaf(w4.x, tanh_fast(qv.x + kv.x), sc[q]);
                    sc[q] = fmaf(w4.y, tanh_fast(qv.y + kv.y), sc[q]);
                    sc[q] = fmaf(w4.z, tanh_fast(qv.z + kv.z), sc[q]);
                    sc[q] = fmaf(w4.w, tanh_fast(qv.w + kv.w), sc[q]);
                }
            }
        }

        __syncthreads();
        if (c < 6) {
            if (stage_ok) {
                float* dst = &kbuf[(c & 1) * KBUF_FLOATS + tid * KB_STRIDE];
                const float* src = &khg[(c + 2) * 32];
                #pragma unroll
                for (int j = 0; j < 8; ++j)
                    cp_async16(&dst[j * 4], &src[j * 4]);
            }
            cp_async_commit();
        }
    }

    // ---- per-q max over this block's keys (masked lanes -> -1e30) ----
    #pragma unroll
    for (int q = 0; q < 8; ++q) {
        float v = stage_ok ? sc[q] : -1e30f;
        sc[q] = v;
        #pragma unroll
        for (int o = 16; o; o >>= 1) v = fmaxf(v, __shfl_xor_sync(0xffffffffu, v, o));
        if (lane == 0) red1[q * 4 + w] = v;
    }
    __syncthreads();
    if (tid < 32) {                    // 32 = 8q x 4w, quad-reduce
        float v = red1[tid];
        v = fmaxf(v, __shfl_xor_sync(0xffffffffu, v, 1));
        v = fmaxf(v, __shfl_xor_sync(0xffffffffu, v, 2));
        if ((tid & 3) == 0) {
            fin_s[tid >> 2] = v;
            g_pm[bx * 8 + (tid >> 2)] = v;
        }
    }
    __syncthreads();

    // ---- unnormalized p + per-q partial sum ----
    #pragma unroll
    for (int q = 0; q < 8; ++q) {
        float p = ex2_fast((sc[q] - fin_s[q]) * L2E);   // masked -> 0
        attn_s[q * KEYS_PB + tid] = p;
        float v = p;
        #pragma unroll
        for (int o = 16; o; o >>= 1) v += __shfl_xor_sync(0xffffffffu, v, o);
        if (lane == 0) red1[q * 4 + w] = v;
    }
    __syncthreads();
    if (tid < 32) {
        float v = red1[tid];
        v += __shfl_xor_sync(0xffffffffu, v, 1);
        v += __shfl_xor_sync(0xffffffffu, v, 2);
        if ((tid & 3) == 0) g_ps[bx * 8 + (tid >> 2)] = v;
    }
    __syncthreads();

    // ---- partial output: o_p[q][v] = sum_{k valid in block} p * V ----
    const int klim = min(KEYS_PB, vlen - kbase);
    const int v0 = tid * 2;                     // 2 v-columns per thread
    const float* vp = values + ((size_t)b * 512 + kbase) * 256 + v0;
    float acc[8][2] = {};
    for (int k = 0; k < klim; ++k) {
        float2 vv = *(const float2*)&vp[(size_t)k * 256];
        #pragma unroll
        for (int q = 0; q < 8; ++q) {
            float a = attn_s[q * KEYS_PB + k];
            acc[q][0] = fmaf(a, vv.x, acc[q][0]);
            acc[q][1] = fmaf(a, vv.y, acc[q][1]);
        }
    }
    #pragma unroll
    for (int q = 0; q < 8; ++q)
        *(float2*)&g_po[((size_t)(bx * 8 + q)) * 256 + v0] =
            make_float2(acc[q][0], acc[q][1]);
}

// ----------------------------------------------------------------------------
// Combine kernel: merge the 4 k-split partials per query row.
// Grid: 128 blocks = (b, qt).  Block: 256 threads = one v column each.
// out = sum_ks w_ks*o_ks / sum_ks w_ks*s_ks,  w_ks = 2^((m_ks - M)*log2e).
// Empty partials have m=-1e30 -> w=0, and o stays 0 -> contribute nothing.
// ----------------------------------------------------------------------------
__global__ __launch_bounds__(256)
void combine_kernel(float* __restrict__ out) {
    const int bx = blockIdx.x;
    const int b  = bx >> 3;
    const int qt = bx & 7;
    const int v  = threadIdx.x;
    const int pb = b * 32 + qt * 4;             // base partial-block index

    #pragma unroll
    for (int q = 0; q < 8; ++q) {
        float m0 = g_pm[(pb + 0) * 8 + q];
        float m1 = g_pm[(pb + 1) * 8 + q];
        float m2 = g_pm[(pb + 2) * 8 + q];
        float m3 = g_pm[(pb + 3) * 8 + q];
        float M = fmaxf(fmaxf(m0, m1), fmaxf(m2, m3));
        float w0 = ex2_fast((m0 - M) * L2E);
        float w1 = ex2_fast((m1 - M) * L2E);
        float w2 = ex2_fast((m2 - M) * L2E);
        float w3 = ex2_fast((m3 - M) * L2E);
        float den = w0 * g_ps[(pb + 0) * 8 + q] + w1 * g_ps[(pb + 1) * 8 + q]
                  + w2 * g_ps[(pb + 2) * 8 + q] + w3 * g_ps[(pb + 3) * 8 + q];
        float num = w0 * g_po[((size_t)((pb + 0) * 8 + q)) * 256 + v]
                  + w1 * g_po[((size_t)((pb + 1) * 8 + q)) * 256 + v]
                  + w2 * g_po[((size_t)((pb + 2) * 8 + q)) * 256 + v]
                  + w3 * g_po[((size_t)((pb + 3) * 8 + q)) * 256 + v];
        out[((size_t)(b * 64 + qt * 8 + q)) * 256 + v] = num * rcp_fast(den);
    }
}

// ----------------------------------------------------------------------------
extern "C" void kernel_launch(void* const* d_in, const int* in_sizes, int n_in,
                              void* d_out, int out_size) {
    (void)in_sizes; (void)n_in; (void)out_size;
    const float* queries = (const float*)d_in[0];   // [16,64,256]
    const float* keys    = (const float*)d_in[1];   // [16,512,256]
    const float* values  = (const float*)d_in[2];   // [16,512,256]
    const int*   vlens   = (const int*)  d_in[3];   // [16]
    const float* Wq      = (const float*)d_in[4];   // [256,256]
    const float* Wk      = (const float*)d_in[5];   // [256,256]
    const float* wv      = (const float*)d_in[6];   // [256]
    float* out = (float*)d_out;                     // [16,64,256]

    float *qh = nullptr, *kh = nullptr;
    cudaGetSymbolAddress((void**)&qh, g_qh);
    cudaGetSymbolAddress((void**)&kh, g_kh);

    cudaFuncSetAttribute(attn_partial_kernel,
                         cudaFuncAttributeMaxDynamicSharedMemorySize,
                         PA_SMEM_BYTES);

    proj_kernel<<<dim3(2, 72), 256>>>(queries, keys, Wq, Wk, qh, kh);
    attn_partial_kernel<<<512, 128, PA_SMEM_BYTES>>>(values, vlens, wv);
    combine_kernel<<<128, 256>>>(out);
}

// round 14
// speedup vs baseline: 1.6299x; 1.1982x over previous
#include <cuda_runtime.h>

// ============================================================================
// AdditiveAttention: out = softmax_k( sum_h w_v[h]*tanh(qW_q + kW_k) ) @ V
// B=16, NQ=64, NK=512, QS=KS=H=VD=256, fp32.
//
// R14 = R13 (split-K partial softmax, unchanged) + tf32 tensor-core projection.
// R13 profile: proj at 39.6us = 83% of the fp32 FFMA roofline (~32us floor) ->
// only the tensor core goes faster. mma.sync m16n8k8 tf32, cvt.rna inputs
// (unbiased rounding; truncation would systematically scale scores by ~1e-3).
// Key-proj blocks fully beyond vlen exit early (partial never reads them).
// ============================================================================

// scratch (allocation-free rule -> __device__ globals; zero-initialized)
__device__ float g_qh[16 * 64 * 256];        // 4 MB: queries @ W_q
__device__ float g_kh[16 * 512 * 256];       // 8 MB: keys @ W_k
__device__ float g_po[512 * 8 * 256];        // 4 MB: partial outputs
__device__ float g_pm[512 * 8];              // partial maxes
__device__ float g_ps[512 * 8];              // partial sums

#define L2E 1.4426950408889634f

__device__ __forceinline__ float tanh_fast(float x) {
    float r; asm("tanh.approx.f32 %0, %1;" : "=f"(r) : "f"(x)); return r;
}
__device__ __forceinline__ float ex2_fast(float x) {
    float r; asm("ex2.approx.f32 %0, %1;" : "=f"(r) : "f"(x)); return r;
}
__device__ __forceinline__ float rcp_fast(float x) {
    float r; asm("rcp.approx.f32 %0, %1;" : "=f"(r) : "f"(x)); return r;
}
__device__ __forceinline__ unsigned f2tf32(float x) {
    unsigned u; asm("cvt.rna.tf32.f32 %0, %1;" : "=r"(u) : "f"(x)); return u;
}
__device__ __forceinline__ void cp_async16(void* smem_dst, const void* gmem_src) {
    unsigned s = (unsigned)__cvta_generic_to_shared(smem_dst);
    asm volatile("cp.async.cg.shared.global [%0], [%1], 16;\n" :: "r"(s), "l"(gmem_src));
}
__device__ __forceinline__ void cp_async_commit() {
    asm volatile("cp.async.commit_group;\n" ::);
}
__device__ __forceinline__ void cp_async_wait1() {
    asm volatile("cp.async.wait_group 1;\n" ::);
}
__device__ __forceinline__ void cp_async_wait0() {
    asm volatile("cp.async.wait_group 0;\n" ::);
}

// ----------------------------------------------------------------------------
// tf32 tensor-core projection GEMM.
// Logical M = 1024 (queries) + 8192 (keys); N = 256, K = 256.
// BM=64, BN=128, BK=16. 256 threads = 8 warps (2 m x 4 n), warp tile 32x32:
// 2 m-tiles (16) x 4 n-tiles (8), k-step 8 -> 8 mma per k-step.
// As[64][20] (stride 20: frag banks 0-3,20-23,8-11,28-31,16-19,4-7,24-27,12-15
// all distinct; rows 16B-aligned). Bs[16][140] (stride 140: banks t*12+g
// distinct; rows 16B-aligned). Grid (2,144) = 288 blocks, occ 2 -> one wave.
// ----------------------------------------------------------------------------
#define AS_S 20
#define BS_S 140

__global__ __launch_bounds__(256, 2)
void proj_tf32_kernel(const float* __restrict__ queries,
                      const float* __restrict__ keys,
                      const float* __restrict__ Wq,
                      const float* __restrict__ Wk,
                      const int* __restrict__ valid_lens,
                      float* __restrict__ qh,
                      float* __restrict__ kh) {
    __shared__ unsigned As[64 * AS_S];
    __shared__ unsigned Bs[16 * BS_S];

    const int tid    = threadIdx.x;
    const int warp   = tid >> 5;
    const int lane   = tid & 31;
    const int g      = lane >> 2;        // 0..7
    const int t      = lane & 3;         // 0..3
    const int warp_m = warp & 1;         // 0..1 -> 32 rows
    const int warp_n = warp >> 1;        // 0..3 -> 32 cols
    const int bm     = blockIdx.y * 64;
    const int bn     = blockIdx.x * 128;

    const float* A; const float* W; float* C; int rowbase;
    if (bm < 1024) { A = queries; W = Wq; C = qh; rowbase = bm; }
    else {
        A = keys; W = Wk; C = kh; rowbase = bm - 1024;
        // skip key blocks fully beyond this batch's valid length
        if ((rowbase & 511) >= valid_lens[rowbase >> 9]) return;
    }

    // staging assignments
    const int arow = tid >> 2;           // 0..63
    const int acol = (tid & 3) * 4;      // 0/4/8/12
    const int brow = tid >> 4;           // 0..15
    const int bcol = (tid & 15) * 4;     // 0..60 (plus +64 for second half)

    float acc[2][4][4] = {};

    // prefetch k0 = 0
    float4 av  = *(const float4*)&A[(rowbase + arow) * 256 + acol];
    float4 bv0 = *(const float4*)&W[brow * 256 + bn + bcol];
    float4 bv1 = *(const float4*)&W[brow * 256 + bn + bcol + 64];

    for (int k0 = 0; k0 < 256; k0 += 16) {
        // store staged tf32 data (consumes prefetched regs)
        {
            uint4 ua = make_uint4(f2tf32(av.x), f2tf32(av.y),
                                  f2tf32(av.z), f2tf32(av.w));
            *(uint4*)&As[arow * AS_S + acol] = ua;
            uint4 ub0 = make_uint4(f2tf32(bv0.x), f2tf32(bv0.y),
                                   f2tf32(bv0.z), f2tf32(bv0.w));
            uint4 ub1 = make_uint4(f2tf32(bv1.x), f2tf32(bv1.y),
                                   f2tf32(bv1.z), f2tf32(bv1.w));
            *(uint4*)&Bs[brow * BS_S + bcol]      = ub0;
            *(uint4*)&Bs[brow * BS_S + bcol + 64] = ub1;
        }
        __syncthreads();

        // prefetch next k-chunk (overlaps with the mma compute below)
        if (k0 + 16 < 256) {
            av  = *(const float4*)&A[(rowbase + arow) * 256 + k0 + 16 + acol];
            bv0 = *(const float4*)&W[(k0 + 16 + brow) * 256 + bn + bcol];
            bv1 = *(const float4*)&W[(k0 + 16 + brow) * 256 + bn + bcol + 64];
        }

        #pragma unroll
        for (int ks = 0; ks < 16; ks += 8) {
            unsigned a[2][4], b[4][2];
            #pragma unroll
            for (int mt = 0; mt < 2; ++mt) {
                const int row = warp_m * 32 + mt * 16;
                a[mt][0] = As[(row + g)     * AS_S + ks + t];
                a[mt][1] = As[(row + g + 8) * AS_S + ks + t];
                a[mt][2] = As[(row + g)     * AS_S + ks + t + 4];
                a[mt][3] = As[(row + g + 8) * AS_S + ks + t + 4];
            }
            #pragma unroll
            for (int nt = 0; nt < 4; ++nt) {
                const int col = warp_n * 32 + nt * 8;
                b[nt][0] = Bs[(ks + t)     * BS_S + col + g];
                b[nt][1] = Bs[(ks + t + 4) * BS_S + col + g];
            }
            #pragma unroll
            for (int mt = 0; mt < 2; ++mt)
                #pragma unroll
                for (int nt = 0; nt < 4; ++nt)
                    asm volatile(
                        "mma.sync.aligned.m16n8k8.row.col.f32.tf32.tf32.f32 "
                        "{%0,%1,%2,%3}, {%4,%5,%6,%7}, {%8,%9}, {%0,%1,%2,%3};"
                        : "+f"(acc[mt][nt][0]), "+f"(acc[mt][nt][1]),
                          "+f"(acc[mt][nt][2]), "+f"(acc[mt][nt][3])
                        : "r"(a[mt][0]), "r"(a[mt][1]),
                          "r"(a[mt][2]), "r"(a[mt][3]),
                          "r"(b[nt][0]), "r"(b[nt][1]));
        }
        __syncthreads();   // protect As/Bs before next iteration's stores
    }

    // epilogue: c0=(g,2t) c1=(g,2t+1) c2=(g+8,2t) c3=(g+8,2t+1)
    #pragma unroll
    for (int mt = 0; mt < 2; ++mt) {
        #pragma unroll
        for (int nt = 0; nt < 4; ++nt) {
            const int row = rowbase + warp_m * 32 + mt * 16 + g;
            const int col = bn + warp_n * 32 + nt * 8 + 2 * t;
            *(float2*)&C[(size_t)row * 256 + col] =
                make_float2(acc[mt][nt][0], acc[mt][nt][1]);
            *(float2*)&C[(size_t)(row + 8) * 256 + col] =
                make_float2(acc[mt][nt][2], acc[mt][nt][3]);
        }
    }
}

// ----------------------------------------------------------------------------
// Partial-attention kernel (unchanged from R13).
// Grid: 512 = b*32 + qt*4 + ks.   Block: 128 threads = 4 warps.
// ----------------------------------------------------------------------------
#define KB_STRIDE 36
#define KEYS_PB 128
#define KBUF_FLOATS (KEYS_PB * KB_STRIDE)
#define PA_SMEM_FLOATS (2 * KBUF_FLOATS + 8 * 256 + 256 + 8 * KEYS_PB + 32 + 8)
#define PA_SMEM_BYTES  (PA_SMEM_FLOATS * 4)

__global__ __launch_bounds__(128, 4)
void attn_partial_kernel(const float* __restrict__ values,
                         const int* __restrict__ valid_lens,
                         const float* __restrict__ w_v) {
    extern __shared__ float sm[];
    float* kbuf   = sm;
    float* qh_s   = kbuf + 2 * KBUF_FLOATS;
    float* wv_s   = qh_s + 8 * 256;
    float* attn_s = wv_s + 256;
    float* red1   = attn_s + 8 * KEYS_PB;
    float* fin_s  = red1 + 32;

    const int tid   = threadIdx.x;
    const int bx    = blockIdx.x;
    const int b     = bx >> 5;
    const int qt    = (bx >> 2) & 7;
    const int ks    = bx & 3;
    const int kbase = ks * KEYS_PB;
    const int vlen  = valid_lens[b];

    if (kbase >= vlen) {
        if (tid < 8) {
            g_pm[bx * 8 + tid] = -1e30f;
            g_ps[bx * 8 + tid] = 0.0f;
        }
        return;
    }

    const int w    = tid >> 5;
    const int lane = tid & 31;
    const int key  = kbase + tid;
    const bool stage_ok  = key < vlen;
    const bool warp_live = (kbase + w * 32) < vlen;
    const int q0   = qt * 8;

    for (int i = tid; i < 512; i += 128)
        *(float4*)&qh_s[i * 4] =
            *(const float4*)&g_qh[((size_t)(b * 64 + q0)) * 256 + i * 4];
    if (tid < 64)
        *(float4*)&wv_s[tid * 4] = *(const float4*)&w_v[tid * 4];

    const float* khg = &g_kh[((size_t)b * 512 + key) * 256];
    #pragma unroll
    for (int pre = 0; pre < 2; ++pre) {
        if (stage_ok) {
            float* dst = &kbuf[pre * KBUF_FLOATS + tid * KB_STRIDE];
            const float* src = &khg[pre * 32];
            #pragma unroll
            for (int j = 0; j < 8; ++j)
                cp_async16(&dst[j * 4], &src[j * 4]);
        }
        cp_async_commit();
    }

    float sc[8] = {0.f, 0.f, 0.f, 0.f, 0.f, 0.f, 0.f, 0.f};

    #pragma unroll 1
    for (int c = 0; c < 8; ++c) {
        if (c < 7) cp_async_wait1(); else cp_async_wait0();
        __syncthreads();

        if (warp_live) {
            const float* kb = &kbuf[(c & 1) * KBUF_FLOATS + tid * KB_STRIDE];
            const int hbase = c * 32;
            #pragma unroll 2
            for (int i = 0; i < 8; ++i) {
                float4 kv = *(const float4*)&kb[i * 4];
                float4 w4 = *(const float4*)&wv_s[hbase + i * 4];
                #pragma unroll
                for (int q = 0; q < 8; ++q) {
                    float4 qv = *(const float4*)&qh_s[q * 256 + hbase + i * 4];
                    sc[q] = fmaf(w4.x, tanh_fast(qv.x + kv.x), sc[q]);
                    sc[q] = fmaf(w4.y, tanh_fast(qv.y + kv.y), sc[q]);
                    sc[q] = fmaf(w4.z, tanh_fast(qv.z + kv.z), sc[q]);
                    sc[q] = fmaf(w4.w, tanh_fast(qv.w + kv.w), sc[q]);
                }
            }
        }

        __syncthreads();
        if (c < 6) {
            if (stage_ok) {
                float* dst = &kbuf[(c & 1) * KBUF_FLOATS + tid * KB_STRIDE];
                const float* src = &khg[(c + 2) * 32];
                #pragma unroll
                for (int j = 0; j < 8; ++j)
                    cp_async16(&dst[j * 4], &src[j * 4]);
            }
            cp_async_commit();
        }
    }

    #pragma unroll
    for (int q = 0; q < 8; ++q) {
        float v = stage_ok ? sc[q] : -1e30f;
        sc[q] = v;
        #pragma unroll
        for (int o = 16; o; o >>= 1) v = fmaxf(v, __shfl_xor_sync(0xffffffffu, v, o));
        if (lane == 0) red1[q * 4 + w] = v;
    }
    __syncthreads();
    if (tid < 32) {
        float v = red1[tid];
        v = fmaxf(v, __shfl_xor_sync(0xffffffffu, v, 1));
        v = fmaxf(v, __shfl_xor_sync(0xffffffffu, v, 2));
        if ((tid & 3) == 0) {
            fin_s[tid >> 2] = v;
            g_pm[bx * 8 + (tid >> 2)] = v;
        }
    }
    __syncthreads();

    #pragma unroll
    for (int q = 0; q < 8; ++q) {
        float p = ex2_fast((sc[q] - fin_s[q]) * L2E);
        attn_s[q * KEYS_PB + tid] = p;
        float v = p;
        #pragma unroll
        for (int o = 16; o; o >>= 1) v += __shfl_xor_sync(0xffffffffu, v, o);
        if (lane == 0) red1[q * 4 + w] = v;
    }
    __syncthreads();
    if (tid < 32) {
        float v = red1[tid];
        v += __shfl_xor_sync(0xffffffffu, v, 1);
        v += __shfl_xor_sync(0xffffffffu, v, 2);
        if ((tid & 3) == 0) g_ps[bx * 8 + (tid >> 2)] = v;
    }
    __syncthreads();

    const int klim = min(KEYS_PB, vlen - kbase);
    const int v0 = tid * 2;
    const float* vp = values + ((size_t)b * 512 + kbase) * 256 + v0;
    float acc[8][2] = {};
    for (int k = 0; k < klim; ++k) {
        float2 vv = *(const float2*)&vp[(size_t)k * 256];
        #pragma unroll
        for (int q = 0; q < 8; ++q) {
            float a = attn_s[q * KEYS_PB + k];
            acc[q][0] = fmaf(a, vv.x, acc[q][0]);
            acc[q][1] = fmaf(a, vv.y, acc[q][1]);
        }
    }
    #pragma unroll
    for (int q = 0; q < 8; ++q)
        *(float2*)&g_po[((size_t)(bx * 8 + q)) * 256 + v0] =
            make_float2(acc[q][0], acc[q][1]);
}

// ----------------------------------------------------------------------------
// Combine kernel (unchanged from R13).
// ----------------------------------------------------------------------------
__global__ __launch_bounds__(256)
void combine_kernel(float* __restrict__ out) {
    const int bx = blockIdx.x;
    const int b  = bx >> 3;
    const int qt = bx & 7;
    const int v  = threadIdx.x;
    const int pb = b * 32 + qt * 4;

    #pragma unroll
    for (int q = 0; q < 8; ++q) {
        float m0 = g_pm[(pb + 0) * 8 + q];
        float m1 = g_pm[(pb + 1) * 8 + q];
        float m2 = g_pm[(pb + 2) * 8 + q];
        float m3 = g_pm[(pb + 3) * 8 + q];
        float M = fmaxf(fmaxf(m0, m1), fmaxf(m2, m3));
        float w0 = ex2_fast((m0 - M) * L2E);
        float w1 = ex2_fast((m1 - M) * L2E);
        float w2 = ex2_fast((m2 - M) * L2E);
        float w3 = ex2_fast((m3 - M) * L2E);
        float den = w0 * g_ps[(pb + 0) * 8 + q] + w1 * g_ps[(pb + 1) * 8 + q]
                  + w2 * g_ps[(pb + 2) * 8 + q] + w3 * g_ps[(pb + 3) * 8 + q];
        float num = w0 * g_po[((size_t)((pb + 0) * 8 + q)) * 256 + v]
                  + w1 * g_po[((size_t)((pb + 1) * 8 + q)) * 256 + v]
                  + w2 * g_po[((size_t)((pb + 2) * 8 + q)) * 256 + v]
                  + w3 * g_po[((size_t)((pb + 3) * 8 + q)) * 256 + v];
        out[((size_t)(b * 64 + qt * 8 + q)) * 256 + v] = num * rcp_fast(den);
    }
}

// ----------------------------------------------------------------------------
extern "C" void kernel_launch(void* const* d_in, const int* in_sizes, int n_in,
                              void* d_out, int out_size) {
    (void)in_sizes; (void)n_in; (void)out_size;
    const float* queries = (const float*)d_in[0];   // [16,64,256]
    const float* keys    = (const float*)d_in[1];   // [16,512,256]
    const float* values  = (const float*)d_in[2];   // [16,512,256]
    const int*   vlens   = (const int*)  d_in[3];   // [16]
    const float* Wq      = (const float*)d_in[4];   // [256,256]
    const float* Wk      = (const float*)d_in[5];   // [256,256]
    const float* wv      = (const float*)d_in[6];   // [256]
    float* out = (float*)d_out;                     // [16,64,256]

    float *qh = nullptr, *kh = nullptr;
    cudaGetSymbolAddress((void**)&qh, g_qh);
    cudaGetSymbolAddress((void**)&kh, g_kh);

    cudaFuncSetAttribute(attn_partial_kernel,
                         cudaFuncAttributeMaxDynamicSharedMemorySize,
                         PA_SMEM_BYTES);

    proj_tf32_kernel<<<dim3(2, 144), 256>>>(queries, keys, Wq, Wk, vlens, qh, kh);
    attn_partial_kernel<<<512, 128, PA_SMEM_BYTES>>>(values, vlens, wv);
    combine_kernel<<<128, 256>>>(out);
}